// round 4
// baseline (speedup 1.0000x reference)
#include <cuda_runtime.h>

// ---------------------------------------------------------------------------
// CustomLSTM: B=2048, T=256, I=5, H=50, O=1
//
// R4 = R3 fused-gate design with the alignment fix (x rows padded to 48B).
//   256 blocks x 400 threads, NB=8 batches/block, 2 blocks/SM.
//   Thread (ub, uj) computes ALL FOUR gates of hidden unit uj for batch ub,
//   then updates c/h locally -> gates never leave registers; ONE barrier per
//   step (h double-buffered in shared). Weights in shared (48KB, 240B row
//   stride, conflict-free). f32x2 FMA packs k. x prefetched one step ahead.
// ---------------------------------------------------------------------------

typedef unsigned long long ull;

constexpr int T   = 256;
constexpr int I   = 5;
constexpr int H   = 50;
constexpr int NB  = 8;            // batches per block
constexpr int NTH = NB * H;       // 400 threads
constexpr int NBLK = 2048 / NB;   // 256 blocks
constexpr int HROW = 52;          // h row stride (floats) -> 208B, 16B-aligned
constexpr int WCH  = 15;          // float4 chunks per weight row: 13 h + 2 x
constexpr int XROW = 6;           // x row stride in ulls -> 48B, 16B-aligned
// dynamic smem layout (bytes)
constexpr int WSM_BYTES  = 4 * H * WCH * 16;          // 48000
constexpr int HSF_FLOATS = 2 * NB * HROW;             // 832
constexpr int HSF_OFF    = WSM_BYTES;                 // 48000 (16B aligned)
constexpr int XB_OFF     = HSF_OFF + HSF_FLOATS * 4;  // 51328 (16B aligned)
constexpr int XB_ULL     = 2 * NB * XROW;             // 96
constexpr int SMEM_BYTES = XB_OFF + XB_ULL * 8;       // 52096

__device__ __forceinline__ ull fma2(ull a, ull b, ull c) {
    ull d;
    asm("fma.rn.f32x2 %0, %1, %2, %3;" : "=l"(d) : "l"(a), "l"(b), "l"(c));
    return d;
}
__device__ __forceinline__ ull pack2(float x, float y) {
    ull r;
    asm("mov.b64 %0, {%1, %2};" : "=l"(r) : "f"(x), "f"(y));
    return r;
}
__device__ __forceinline__ float2 unpack2(ull v) {
    float2 r;
    asm("mov.b64 {%0, %1}, %2;" : "=f"(r.x), "=f"(r.y) : "l"(v));
    return r;
}
__device__ __forceinline__ float sigf(float x) {
    return __fdividef(1.0f, 1.0f + __expf(-x));
}
__device__ __forceinline__ float tanh_fast(float x) {
    float a = fabsf(x);
    float e = __expf(-2.0f * a);
    float t = __fdividef(1.0f - e, 1.0f + e);
    return copysignf(t, x);
}

__global__ void __launch_bounds__(NTH, 2) lstm_fused_kernel(
    const float* __restrict__ x,
    const float* __restrict__ Wxf, const float* __restrict__ bxf,
    const float* __restrict__ Wxi, const float* __restrict__ bxi,
    const float* __restrict__ Wxc, const float* __restrict__ bxc,
    const float* __restrict__ Wxo, const float* __restrict__ bxo,
    const float* __restrict__ Whf, const float* __restrict__ bhf,
    const float* __restrict__ Whi, const float* __restrict__ bhi,
    const float* __restrict__ Whc, const float* __restrict__ bhc,
    const float* __restrict__ Who, const float* __restrict__ bho,
    const float* __restrict__ bf,  const float* __restrict__ bi,
    const float* __restrict__ bc,  const float* __restrict__ bo,
    const float* __restrict__ Wfc, const float* __restrict__ bfc,
    float* __restrict__ out)
{
    extern __shared__ __align__(16) char sm_raw[];
    float4* wsm = (float4*)sm_raw;                 // [4][H][WCH]
    float*  hsf = (float*)(sm_raw + HSF_OFF);      // [2][NB][HROW]
    ull*    xb  = (ull*)(sm_raw + XB_OFF);         // [2][NB][XROW]

    const int tid = threadIdx.x;
    const int b0  = blockIdx.x * NB;
    const int ub  = tid & 7;       // batch within block (tid = uj*8 + ub)
    const int uj  = tid >> 3;      // hidden unit

    // ---- stage weights into shared: wsm[q][uj][c], c<13: Wh[4c..4c+3],
    //      c==13: Wx[0..3], c==14: (Wx[4],0,0,0). Pads are zero.
    {
        const float* Wh[4] = {Whf, Whi, Whc, Who};
        const float* Wx[4] = {Wxf, Wxi, Wxc, Wxo};
        for (int idx = tid; idx < 4 * H * WCH; idx += NTH) {
            int q = idx / (H * WCH);
            int r = idx - q * (H * WCH);
            int u = r / WCH;
            int c = r - u * WCH;
            float4 v = make_float4(0.f, 0.f, 0.f, 0.f);
            if (c < 13) {
                const float* p = Wh[q] + u * H + 4 * c;
                int k0 = 4 * c;
                v.x = p[0];
                if (k0 + 1 < H) v.y = p[1];
                if (k0 + 2 < H) v.z = p[2];
                if (k0 + 3 < H) v.w = p[3];
            } else if (c == 13) {
                const float* p = Wx[q] + u * I;
                v = make_float4(p[0], p[1], p[2], p[3]);
            } else {
                v.x = Wx[q][u * I + 4];
            }
            wsm[idx] = v;
        }
    }
    // ---- zero h (both buffers incl. pads) and x buffers (pads must be 0)
    for (int idx = tid; idx < HSF_FLOATS; idx += NTH) hsf[idx] = 0.0f;
    for (int idx = tid; idx < XB_ULL; idx += NTH) xb[idx] = 0ull;

    // ---- per-thread combined biases (one per gate)
    const float bt0 = bxf[uj] + bhf[uj] + bf[uj];
    const float bt1 = bxi[uj] + bhi[uj] + bi[uj];
    const float bt2 = bxc[uj] + bhc[uj] + bc[uj];
    const float bt3 = bxo[uj] + bho[uj] + bo[uj];

    // ---- stage x(t=0)
    if (tid < NB * I) {
        int pb = tid / I, pi = tid - pb * I;
        ((float*)xb)[pb * (2 * XROW) + pi] = x[(size_t)(b0 + pb) * (T * I) + pi];
    }

    // ---- per-gate weight row pointers (ulonglong2 view of float4 rows)
    const ulonglong2* wv = (const ulonglong2*)wsm;
    const ulonglong2* w0p = wv + (0 * H + uj) * WCH;
    const ulonglong2* w1p = wv + (1 * H + uj) * WCH;
    const ulonglong2* w2p = wv + (2 * H + uj) * WCH;
    const ulonglong2* w3p = wv + (3 * H + uj) * WCH;

    float creg = 0.0f;
    __syncthreads();

    // =============================== time loop ==============================
    for (int t = 0; t < T; t++) {
        // prefetch x(t+1) early (latency hidden under the gate GEMV)
        float pf = 0.0f;
        const bool dofetch = (tid < NB * I) && (t + 1 < T);
        if (dofetch) {
            int pb = tid / I, pi = tid - pb * I;
            pf = x[(size_t)(b0 + pb) * (T * I) + (t + 1) * I + pi];
        }

        const float* hb = hsf + (t & 1) * (NB * HROW) + ub * HROW;
        const ull*   xr = xb + (t & 1) * (NB * XROW) + ub * XROW;
        ulonglong2 xv01 = *(const ulonglong2*)xr;   // (x0,x1),(x2,x3) 16B-aligned
        ull        xv4  = xr[2];                    // (x4, 0)

        ull a0 = pack2(bt0, 0.0f);
        ull a1 = pack2(bt1, 0.0f);
        ull a2 = pack2(bt2, 0.0f);
        ull a3 = pack2(bt3, 0.0f);

#pragma unroll
        for (int c = 0; c < 13; c++) {
            ulonglong2 hv = *(const ulonglong2*)(hb + 4 * c);  // h[4c..4c+3]
            ulonglong2 q0 = w0p[c];
            ulonglong2 q1 = w1p[c];
            ulonglong2 q2 = w2p[c];
            ulonglong2 q3 = w3p[c];
            a0 = fma2(hv.x, q0.x, a0); a0 = fma2(hv.y, q0.y, a0);
            a1 = fma2(hv.x, q1.x, a1); a1 = fma2(hv.y, q1.y, a1);
            a2 = fma2(hv.x, q2.x, a2); a2 = fma2(hv.y, q2.y, a2);
            a3 = fma2(hv.x, q3.x, a3); a3 = fma2(hv.y, q3.y, a3);
        }
        // x contribution (chunks 13,14)
        {
            ulonglong2 q0 = w0p[13], q1 = w1p[13], q2 = w2p[13], q3 = w3p[13];
            a0 = fma2(xv01.x, q0.x, a0); a0 = fma2(xv01.y, q0.y, a0);
            a1 = fma2(xv01.x, q1.x, a1); a1 = fma2(xv01.y, q1.y, a1);
            a2 = fma2(xv01.x, q2.x, a2); a2 = fma2(xv01.y, q2.y, a2);
            a3 = fma2(xv01.x, q3.x, a3); a3 = fma2(xv01.y, q3.y, a3);
            a0 = fma2(xv4, w0p[14].x, a0);
            a1 = fma2(xv4, w1p[14].x, a1);
            a2 = fma2(xv4, w2p[14].x, a2);
            a3 = fma2(xv4, w3p[14].x, a3);
        }

        float2 f0 = unpack2(a0), f1 = unpack2(a1);
        float2 f2 = unpack2(a2), f3 = unpack2(a3);
        float gf = f0.x + f0.y;
        float gi = f1.x + f1.y;
        float gc = f2.x + f2.y;
        float go = f3.x + f3.y;

        creg = sigf(gf) * creg + sigf(gi) * tanh_fast(gc);
        float hn = sigf(go) * tanh_fast(creg);

        hsf[((t + 1) & 1) * (NB * HROW) + ub * HROW + uj] = hn;
        if (dofetch) {
            int pb = tid / I, pi = tid - pb * I;
            ((float*)xb)[((t + 1) & 1) * (NB * 2 * XROW) + pb * (2 * XROW) + pi] = pf;
        }
        __syncthreads();
    }

    // ---- final projection: out[b] = h_T[b] . Wfc + bfc   (O = 1)
    // last h written to buffer (T & 1) = 0
    if (tid < NB) {
        const float* hp = hsf + tid * HROW;
        float s = bfc[0];
#pragma unroll
        for (int k = 0; k < H; k++) s += hp[k] * Wfc[k];
        out[b0 + tid] = s;
    }
}

extern "C" void kernel_launch(void* const* d_in, const int* in_sizes, int n_in,
                              void* d_out, int out_size)
{
    (void)in_sizes; (void)n_in; (void)out_size;
    const float* x   = (const float*)d_in[0];
    const float* Wxf = (const float*)d_in[1];
    const float* bxf = (const float*)d_in[2];
    const float* Wxi = (const float*)d_in[3];
    const float* bxi = (const float*)d_in[4];
    const float* Wxc = (const float*)d_in[5];
    const float* bxc = (const float*)d_in[6];
    const float* Wxo = (const float*)d_in[7];
    const float* bxo = (const float*)d_in[8];
    const float* Whf = (const float*)d_in[9];
    const float* bhf = (const float*)d_in[10];
    const float* Whi = (const float*)d_in[11];
    const float* bhi = (const float*)d_in[12];
    const float* Whc = (const float*)d_in[13];
    const float* bhc = (const float*)d_in[14];
    const float* Who = (const float*)d_in[15];
    const float* bho = (const float*)d_in[16];
    const float* bf  = (const float*)d_in[17];
    const float* bi  = (const float*)d_in[18];
    const float* bc  = (const float*)d_in[19];
    const float* bo  = (const float*)d_in[20];
    const float* Wfc = (const float*)d_in[21];
    const float* bfc = (const float*)d_in[22];
    float* out = (float*)d_out;

    cudaFuncSetAttribute(lstm_fused_kernel,
                         cudaFuncAttributeMaxDynamicSharedMemorySize,
                         SMEM_BYTES);

    lstm_fused_kernel<<<NBLK, NTH, SMEM_BYTES>>>(
        x,
        Wxf, bxf, Wxi, bxi, Wxc, bxc, Wxo, bxo,
        Whf, bhf, Whi, bhi, Whc, bhc, Who, bho,
        bf, bi, bc, bo,
        Wfc, bfc,
        out);
}